// round 2
// baseline (speedup 1.0000x reference)
#include <cuda_runtime.h>
#include <math.h>
#include <stdint.h>

#define N_LEVELS   16
#define HASH_SIZE  (1u << 19)
#define HASH_MASK  (HASH_SIZE - 1u)
#define BLOCK      256
#define MAXN       (1 << 20)

// Morton binning: 6 bits/dim -> 2^18 buckets (avg 4 points/bucket at N=1M).
#define BPD        6
#define NB         (1 << (3 * BPD))

__device__ unsigned g_cnt[NB];      // histogram
__device__ unsigned g_off[NB];      // running offsets (consumed by scatter)
__device__ unsigned g_perm[MAXN];   // spatially-clustered processing order

struct Res16 { float r[N_LEVELS]; };

// ---------------------------------------------------------------------------

__device__ __forceinline__ unsigned morton_bucket(float px, float py, float pz) {
    unsigned cx = (unsigned)(px * 64.0f); cx = cx > 63u ? 63u : cx;
    unsigned cy = (unsigned)(py * 64.0f); cy = cy > 63u ? 63u : cy;
    unsigned cz = (unsigned)(pz * 64.0f); cz = cz > 63u ? 63u : cz;
    unsigned key = 0;
    #pragma unroll
    for (int b = 0; b < BPD; ++b) {
        key |= ((cx >> b) & 1u) << (3 * b)
             | ((cy >> b) & 1u) << (3 * b + 1)
             | ((cz >> b) & 1u) << (3 * b + 2);
    }
    return key;
}

__global__ void zero_cnt_kernel() {
    g_cnt[blockIdx.x * blockDim.x + threadIdx.x] = 0u;
}

__global__ void hist_kernel(const float* __restrict__ xin, int n) {
    int j = blockIdx.x * blockDim.x + threadIdx.x;
    if (j >= n) return;
    unsigned b = morton_bucket(xin[3 * j], xin[3 * j + 1], xin[3 * j + 2]);
    atomicAdd(&g_cnt[b], 1u);
}

// Single-block exclusive scan of g_cnt -> g_off. 1024 threads x (NB/1024) each.
__global__ __launch_bounds__(1024) void scan_kernel() {
    __shared__ unsigned s[1024];
    const int t = threadIdx.x;
    const int chunk = NB / 1024;
    const int base = t * chunk;

    unsigned sum = 0;
    for (int k = 0; k < chunk; ++k) sum += g_cnt[base + k];
    s[t] = sum;
    __syncthreads();

    // Hillis-Steele inclusive scan over the 1024 per-thread sums
    for (int off = 1; off < 1024; off <<= 1) {
        unsigned u = (t >= off) ? s[t - off] : 0u;
        __syncthreads();
        s[t] += u;
        __syncthreads();
    }

    unsigned run = s[t] - sum;  // exclusive prefix of this thread's chunk
    for (int k = 0; k < chunk; ++k) {
        unsigned c = g_cnt[base + k];
        g_off[base + k] = run;
        run += c;
    }
}

__global__ void scatter_kernel(const float* __restrict__ xin, int n) {
    int j = blockIdx.x * blockDim.x + threadIdx.x;
    if (j >= n) return;
    unsigned b = morton_bucket(xin[3 * j], xin[3 * j + 1], xin[3 * j + 2]);
    unsigned p = atomicAdd(&g_off[b], 1u);
    g_perm[p] = (unsigned)j;
}

// ---------------------------------------------------------------------------

__device__ __forceinline__ float2 lerp2(float2 a, float2 b, float t) {
    float2 o;
    o.x = fmaf(t, b.x - a.x, a.x);
    o.y = fmaf(t, b.y - a.y, a.y);
    return o;
}

__global__ __launch_bounds__(BLOCK) void hash_encode_kernel(
    const float* __restrict__ xin,
    const float* __restrict__ tables,
    float* __restrict__ out,
    Res16 rp, int n)
{
    const int j = blockIdx.x * BLOCK + threadIdx.x;
    if (j >= n) return;
    const int i = (int)g_perm[j];   // spatially-clustered order

    const float px = xin[3 * i + 0];
    const float py = xin[3 * i + 1];
    const float pz = xin[3 * i + 2];

    float acc[2 * N_LEVELS];

    #pragma unroll
    for (int L = 0; L < N_LEVELS; ++L) {
        const float res = rp.r[L];
        const float sx = px * res;
        const float sy = py * res;
        const float sz = pz * res;
        const int ix = (int)sx;          // trunc == floor for x >= 0
        const int iy = (int)sy;
        const int iz = (int)sz;
        const float fx = sx - (float)ix;
        const float fy = sy - (float)iy;
        const float fz = sz - (float)iz;

        const unsigned ux0 = (unsigned)ix;
        const unsigned ux1 = ux0 + 1u;
        const unsigned hy0 = (unsigned)iy * 2654435761u;
        const unsigned hy1 = hy0 + 2654435761u;
        const unsigned hz0 = (unsigned)iz * 805459861u;
        const unsigned hz1 = hz0 + 805459861u;

        const unsigned c00 = ux0 ^ hy0;
        const unsigned c10 = ux1 ^ hy0;
        const unsigned c01 = ux0 ^ hy1;
        const unsigned c11 = ux1 ^ hy1;

        const float2* __restrict__ tab =
            reinterpret_cast<const float2*>(tables) + (size_t)L * HASH_SIZE;

        const float2 f000 = __ldg(tab + ((c00 ^ hz0) & HASH_MASK));
        const float2 f100 = __ldg(tab + ((c10 ^ hz0) & HASH_MASK));
        const float2 f010 = __ldg(tab + ((c01 ^ hz0) & HASH_MASK));
        const float2 f110 = __ldg(tab + ((c11 ^ hz0) & HASH_MASK));
        const float2 f001 = __ldg(tab + ((c00 ^ hz1) & HASH_MASK));
        const float2 f101 = __ldg(tab + ((c10 ^ hz1) & HASH_MASK));
        const float2 f011 = __ldg(tab + ((c01 ^ hz1) & HASH_MASK));
        const float2 f111 = __ldg(tab + ((c11 ^ hz1) & HASH_MASK));

        const float2 v00 = lerp2(f000, f100, fx);
        const float2 v10 = lerp2(f010, f110, fx);
        const float2 v01 = lerp2(f001, f101, fx);
        const float2 v11 = lerp2(f011, f111, fx);
        const float2 w0  = lerp2(v00, v10, fy);
        const float2 w1  = lerp2(v01, v11, fy);
        const float2 rr  = lerp2(w0, w1, fz);

        acc[2 * L + 0] = rr.x;
        acc[2 * L + 1] = rr.y;
    }

    // write to the point's ORIGINAL row (output order unchanged)
    float4* o4 = reinterpret_cast<float4*>(out + (size_t)i * (2 * N_LEVELS));
    #pragma unroll
    for (int k = 0; k < 8; ++k) {
        float4 v;
        v.x = acc[4 * k + 0];
        v.y = acc[4 * k + 1];
        v.z = acc[4 * k + 2];
        v.w = acc[4 * k + 3];
        o4[k] = v;
    }
}

// ---------------------------------------------------------------------------

extern "C" void kernel_launch(void* const* d_in, const int* in_sizes, int n_in,
                              void* d_out, int out_size) {
    const float* x      = (const float*)d_in[0];
    const float* tables = (const float*)d_in[1];
    float* out          = (float*)d_out;

    const int n = in_sizes[0] / 3;

    // Resolutions exactly as the reference computes them:
    // growth = (512/16) ** (1/15) in double; res_i = float(int(16 * growth**i))
    Res16 rp;
    const double growth = pow(512.0 / 16.0, 1.0 / (double)(N_LEVELS - 1));
    for (int l = 0; l < N_LEVELS; ++l) {
        double r = 16.0 * pow(growth, (double)l);
        rp.r[l] = (float)(long long)r;
    }

    const int blocks = (n + BLOCK - 1) / BLOCK;

    zero_cnt_kernel<<<NB / 1024, 1024>>>();
    hist_kernel<<<blocks, BLOCK>>>(x, n);
    scan_kernel<<<1, 1024>>>();
    scatter_kernel<<<blocks, BLOCK>>>(x, n);
    hash_encode_kernel<<<blocks, BLOCK>>>(x, tables, out, rp, n);
}

// round 3
// speedup vs baseline: 2.8050x; 2.8050x over previous
#include <cuda_runtime.h>
#include <math.h>
#include <stdint.h>

#define N_LEVELS   16
#define HASH_SIZE  (1u << 19)
#define HASH_MASK  (HASH_SIZE - 1u)
#define BLOCK      256
#define MAXN       (1 << 20)

// Morton binning: 5 bits/dim -> 2^15 buckets (avg 32 points/bucket at N=1M,
// i.e. one warp ~= one spatial cluster of side 1/32).
#define BPD        5
#define NB         (1 << (3 * BPD))

__device__ unsigned g_cnt[NB];
__device__ unsigned g_off[NB];
__device__ unsigned g_perm[MAXN];       // permuted order -> original index
__device__ float    g_xp[MAXN * 3];     // coords in permuted order

struct Res16 { float r[N_LEVELS]; };

// ---------------------------------------------------------------------------

__device__ __forceinline__ unsigned morton_bucket(float px, float py, float pz) {
    unsigned cx = (unsigned)(px * 32.0f); cx = cx > 31u ? 31u : cx;
    unsigned cy = (unsigned)(py * 32.0f); cy = cy > 31u ? 31u : cy;
    unsigned cz = (unsigned)(pz * 32.0f); cz = cz > 31u ? 31u : cz;
    unsigned key = 0;
    #pragma unroll
    for (int b = 0; b < BPD; ++b) {
        key |= ((cx >> b) & 1u) << (3 * b)
             | ((cy >> b) & 1u) << (3 * b + 1)
             | ((cz >> b) & 1u) << (3 * b + 2);
    }
    return key;
}

__global__ void zero_cnt_kernel() {
    g_cnt[blockIdx.x * blockDim.x + threadIdx.x] = 0u;
}

__global__ void hist_kernel(const float* __restrict__ xin, int n) {
    int j = blockIdx.x * blockDim.x + threadIdx.x;
    if (j >= n) return;
    unsigned b = morton_bucket(xin[3 * j], xin[3 * j + 1], xin[3 * j + 2]);
    atomicAdd(&g_cnt[b], 1u);
}

// Single-block vectorized exclusive scan: 1024 threads x 32 buckets (8 uint4).
__global__ __launch_bounds__(1024) void scan_kernel() {
    __shared__ unsigned s[1024];
    const int t = threadIdx.x;
    const uint4* c4 = reinterpret_cast<const uint4*>(g_cnt);
    uint4* o4 = reinterpret_cast<uint4*>(g_off);

    uint4 v[8];
    unsigned sum = 0;
    #pragma unroll
    for (int k = 0; k < 8; ++k) {
        v[k] = c4[t * 8 + k];
        sum += v[k].x + v[k].y + v[k].z + v[k].w;
    }
    s[t] = sum;
    __syncthreads();

    for (int off = 1; off < 1024; off <<= 1) {
        unsigned u = (t >= off) ? s[t - off] : 0u;
        __syncthreads();
        s[t] += u;
        __syncthreads();
    }

    unsigned run = s[t] - sum;   // exclusive prefix of this thread's chunk
    #pragma unroll
    for (int k = 0; k < 8; ++k) {
        uint4 o;
        o.x = run; run += v[k].x;
        o.y = run; run += v[k].y;
        o.z = run; run += v[k].z;
        o.w = run; run += v[k].w;
        o4[t * 8 + k] = o;
    }
}

__global__ void scatter_kernel(const float* __restrict__ xin, int n) {
    int j = blockIdx.x * blockDim.x + threadIdx.x;
    if (j >= n) return;
    const float px = xin[3 * j + 0];
    const float py = xin[3 * j + 1];
    const float pz = xin[3 * j + 2];
    unsigned b = morton_bucket(px, py, pz);
    unsigned p = atomicAdd(&g_off[b], 1u);
    g_perm[p] = (unsigned)j;
    g_xp[3 * p + 0] = px;
    g_xp[3 * p + 1] = py;
    g_xp[3 * p + 2] = pz;
}

// ---------------------------------------------------------------------------

__device__ __forceinline__ float2 lerp2(float2 a, float2 b, float t) {
    float2 o;
    o.x = fmaf(t, b.x - a.x, a.x);
    o.y = fmaf(t, b.y - a.y, a.y);
    return o;
}

__global__ __launch_bounds__(BLOCK) void hash_encode_kernel(
    const float* __restrict__ tables,
    float* __restrict__ out,
    Res16 rp, int n)
{
    __shared__ float    s_acc[BLOCK * 33];   // row-major staged output (pad 33)
    __shared__ unsigned sperm[BLOCK];

    const int base = blockIdx.x * BLOCK;
    const int t = threadIdx.x;
    const int nblk = min(BLOCK, n - base);

    // coalesced staging of permuted coords + perm indices
    for (int k = t; k < 3 * nblk; k += BLOCK) s_acc[k] = g_xp[3 * base + k];
    if (t < nblk) sperm[t] = g_perm[base + t];
    __syncthreads();

    float px = 0.f, py = 0.f, pz = 0.f;
    if (t < nblk) {
        px = s_acc[3 * t + 0];
        py = s_acc[3 * t + 1];
        pz = s_acc[3 * t + 2];
    }
    __syncthreads();   // s_acc about to be reused for output staging

    if (t < nblk) {
        float acc[2 * N_LEVELS];

        #pragma unroll
        for (int L = 0; L < N_LEVELS; ++L) {
            const float res = rp.r[L];
            const float sx = px * res;
            const float sy = py * res;
            const float sz = pz * res;
            const int ix = (int)sx;
            const int iy = (int)sy;
            const int iz = (int)sz;
            const float fx = sx - (float)ix;
            const float fy = sy - (float)iy;
            const float fz = sz - (float)iz;

            const unsigned ux0 = (unsigned)ix;
            const unsigned ux1 = ux0 + 1u;
            const unsigned hy0 = (unsigned)iy * 2654435761u;
            const unsigned hy1 = hy0 + 2654435761u;
            const unsigned hz0 = (unsigned)iz * 805459861u;
            const unsigned hz1 = hz0 + 805459861u;

            const unsigned c00 = ux0 ^ hy0;
            const unsigned c10 = ux1 ^ hy0;
            const unsigned c01 = ux0 ^ hy1;
            const unsigned c11 = ux1 ^ hy1;

            const float2* __restrict__ tab =
                reinterpret_cast<const float2*>(tables) + (size_t)L * HASH_SIZE;

            const float2 f000 = __ldg(tab + ((c00 ^ hz0) & HASH_MASK));
            const float2 f100 = __ldg(tab + ((c10 ^ hz0) & HASH_MASK));
            const float2 f010 = __ldg(tab + ((c01 ^ hz0) & HASH_MASK));
            const float2 f110 = __ldg(tab + ((c11 ^ hz0) & HASH_MASK));
            const float2 f001 = __ldg(tab + ((c00 ^ hz1) & HASH_MASK));
            const float2 f101 = __ldg(tab + ((c10 ^ hz1) & HASH_MASK));
            const float2 f011 = __ldg(tab + ((c01 ^ hz1) & HASH_MASK));
            const float2 f111 = __ldg(tab + ((c11 ^ hz1) & HASH_MASK));

            const float2 v00 = lerp2(f000, f100, fx);
            const float2 v10 = lerp2(f010, f110, fx);
            const float2 v01 = lerp2(f001, f101, fx);
            const float2 v11 = lerp2(f011, f111, fx);
            const float2 w0  = lerp2(v00, v10, fy);
            const float2 w1  = lerp2(v01, v11, fy);
            const float2 rr  = lerp2(w0, w1, fz);

            acc[2 * L + 0] = rr.x;
            acc[2 * L + 1] = rr.y;
        }

        #pragma unroll
        for (int k = 0; k < 2 * N_LEVELS; ++k) s_acc[t * 33 + k] = acc[k];
    }
    __syncthreads();

    // transpose store: each row (point) is exactly one 128B line in out.
    const int wid  = t >> 5;
    const int lane = t & 31;
    const int rend = min((wid + 1) * 32, nblk);
    for (int r = wid * 32; r < rend; ++r) {
        const size_t i = (size_t)sperm[r];
        out[i * (2 * N_LEVELS) + lane] = s_acc[r * 33 + lane];
    }
}

// ---------------------------------------------------------------------------

extern "C" void kernel_launch(void* const* d_in, const int* in_sizes, int n_in,
                              void* d_out, int out_size) {
    const float* x      = (const float*)d_in[0];
    const float* tables = (const float*)d_in[1];
    float* out          = (float*)d_out;

    const int n = in_sizes[0] / 3;

    // Resolutions exactly as the reference computes them.
    Res16 rp;
    const double growth = pow(512.0 / 16.0, 1.0 / (double)(N_LEVELS - 1));
    for (int l = 0; l < N_LEVELS; ++l) {
        double r = 16.0 * pow(growth, (double)l);
        rp.r[l] = (float)(long long)r;
    }

    const int blocks = (n + BLOCK - 1) / BLOCK;

    zero_cnt_kernel<<<NB / 1024, 1024>>>();
    hist_kernel<<<blocks, BLOCK>>>(x, n);
    scan_kernel<<<1, 1024>>>();
    scatter_kernel<<<blocks, BLOCK>>>(x, n);
    hash_encode_kernel<<<blocks, BLOCK>>>(tables, out, rp, n);
}

// round 4
// speedup vs baseline: 3.1052x; 1.1071x over previous
#include <cuda_runtime.h>
#include <math.h>
#include <stdint.h>

#define N_LEVELS   16
#define HASH_SIZE  (1u << 19)
#define HASH_MASK  (HASH_SIZE - 1u)
#define BLOCK      256
#define MAXN       (1 << 20)

// Morton binning: 5 bits/dim -> 2^15 buckets (avg 32 points/bucket at N=1M,
// i.e. one warp ~= one spatial cluster of side 1/32).
#define BPD        5
#define NB         (1 << (3 * BPD))

__device__ unsigned g_cnt[NB];
__device__ unsigned g_off[NB];
__device__ float4   g_pk[MAXN];   // (x, y, z, bitcast(original index)), permuted order

struct Res16 { float r[N_LEVELS]; };

// ---------------------------------------------------------------------------

__device__ __forceinline__ unsigned morton_bucket(float px, float py, float pz) {
    unsigned cx = (unsigned)(px * 32.0f); cx = cx > 31u ? 31u : cx;
    unsigned cy = (unsigned)(py * 32.0f); cy = cy > 31u ? 31u : cy;
    unsigned cz = (unsigned)(pz * 32.0f); cz = cz > 31u ? 31u : cz;
    unsigned key = 0;
    #pragma unroll
    for (int b = 0; b < BPD; ++b) {
        key |= ((cx >> b) & 1u) << (3 * b)
             | ((cy >> b) & 1u) << (3 * b + 1)
             | ((cz >> b) & 1u) << (3 * b + 2);
    }
    return key;
}

__global__ void zero_cnt_kernel() {
    g_cnt[blockIdx.x * blockDim.x + threadIdx.x] = 0u;
}

__global__ void hist_kernel(const float* __restrict__ xin, int n) {
    int j = blockIdx.x * blockDim.x + threadIdx.x;
    if (j >= n) return;
    unsigned b = morton_bucket(xin[3 * j], xin[3 * j + 1], xin[3 * j + 2]);
    atomicAdd(&g_cnt[b], 1u);
}

// Single-block vectorized exclusive scan: 1024 threads x 32 buckets (8 uint4).
__global__ __launch_bounds__(1024) void scan_kernel() {
    __shared__ unsigned s[1024];
    const int t = threadIdx.x;
    const uint4* c4 = reinterpret_cast<const uint4*>(g_cnt);
    uint4* o4 = reinterpret_cast<uint4*>(g_off);

    uint4 v[8];
    unsigned sum = 0;
    #pragma unroll
    for (int k = 0; k < 8; ++k) {
        v[k] = c4[t * 8 + k];
        sum += v[k].x + v[k].y + v[k].z + v[k].w;
    }
    s[t] = sum;
    __syncthreads();

    for (int off = 1; off < 1024; off <<= 1) {
        unsigned u = (t >= off) ? s[t - off] : 0u;
        __syncthreads();
        s[t] += u;
        __syncthreads();
    }

    unsigned run = s[t] - sum;   // exclusive prefix of this thread's chunk
    #pragma unroll
    for (int k = 0; k < 8; ++k) {
        uint4 o;
        o.x = run; run += v[k].x;
        o.y = run; run += v[k].y;
        o.z = run; run += v[k].z;
        o.w = run; run += v[k].w;
        o4[t * 8 + k] = o;
    }
}

__global__ void scatter_kernel(const float* __restrict__ xin, int n) {
    int j = blockIdx.x * blockDim.x + threadIdx.x;
    if (j >= n) return;
    const float px = xin[3 * j + 0];
    const float py = xin[3 * j + 1];
    const float pz = xin[3 * j + 2];
    unsigned b = morton_bucket(px, py, pz);
    unsigned p = atomicAdd(&g_off[b], 1u);
    float4 v;
    v.x = px; v.y = py; v.z = pz; v.w = __uint_as_float((unsigned)j);
    g_pk[p] = v;   // single STG.128, one line per point
}

// ---------------------------------------------------------------------------

__device__ __forceinline__ float2 lerp2(float2 a, float2 b, float t) {
    float2 o;
    o.x = fmaf(t, b.x - a.x, a.x);
    o.y = fmaf(t, b.y - a.y, a.y);
    return o;
}

__global__ __launch_bounds__(BLOCK) void hash_encode_kernel(
    const float* __restrict__ tables,
    float* __restrict__ out,
    Res16 rp, int n)
{
    __shared__ float    s_acc[BLOCK * 33];   // staged output rows (pad 33)
    __shared__ unsigned sperm[BLOCK];

    const int base = blockIdx.x * BLOCK;
    const int t = threadIdx.x;
    const int nblk = min(BLOCK, n - base);
    const int j = base + t;

    if (t < nblk) {
        const float4 pk = g_pk[j];           // coalesced LDG.128
        const float px = pk.x, py = pk.y, pz = pk.z;
        sperm[t] = __float_as_uint(pk.w);

        float acc[2 * N_LEVELS];

        #pragma unroll
        for (int L = 0; L < N_LEVELS; ++L) {
            const float res = rp.r[L];
            const float sx = px * res;
            const float sy = py * res;
            const float sz = pz * res;
            const int ix = (int)sx;          // trunc == floor for x >= 0
            const int iy = (int)sy;
            const int iz = (int)sz;
            const float fx = sx - (float)ix;
            const float fy = sy - (float)iy;
            const float fz = sz - (float)iz;

            const unsigned ux0 = (unsigned)ix;
            const unsigned ux1 = ux0 + 1u;
            const unsigned hy0 = (unsigned)iy * 2654435761u;
            const unsigned hy1 = hy0 + 2654435761u;
            const unsigned hz0 = (unsigned)iz * 805459861u;
            const unsigned hz1 = hz0 + 805459861u;

            const unsigned c00 = ux0 ^ hy0;
            const unsigned c10 = ux1 ^ hy0;
            const unsigned c01 = ux0 ^ hy1;
            const unsigned c11 = ux1 ^ hy1;

            const float2* __restrict__ tab =
                reinterpret_cast<const float2*>(tables) + (size_t)L * HASH_SIZE;

            const float2 f000 = __ldg(tab + ((c00 ^ hz0) & HASH_MASK));
            const float2 f100 = __ldg(tab + ((c10 ^ hz0) & HASH_MASK));
            const float2 f010 = __ldg(tab + ((c01 ^ hz0) & HASH_MASK));
            const float2 f110 = __ldg(tab + ((c11 ^ hz0) & HASH_MASK));
            const float2 f001 = __ldg(tab + ((c00 ^ hz1) & HASH_MASK));
            const float2 f101 = __ldg(tab + ((c10 ^ hz1) & HASH_MASK));
            const float2 f011 = __ldg(tab + ((c01 ^ hz1) & HASH_MASK));
            const float2 f111 = __ldg(tab + ((c11 ^ hz1) & HASH_MASK));

            const float2 v00 = lerp2(f000, f100, fx);
            const float2 v10 = lerp2(f010, f110, fx);
            const float2 v01 = lerp2(f001, f101, fx);
            const float2 v11 = lerp2(f011, f111, fx);
            const float2 w0  = lerp2(v00, v10, fy);
            const float2 w1  = lerp2(v01, v11, fy);
            const float2 rr  = lerp2(w0, w1, fz);

            acc[2 * L + 0] = rr.x;
            acc[2 * L + 1] = rr.y;
        }

        #pragma unroll
        for (int k = 0; k < 2 * N_LEVELS; ++k) s_acc[t * 33 + k] = acc[k];
    }
    __syncthreads();

    // transpose store: each row (point) is exactly one 128B line in out.
    const int wid  = t >> 5;
    const int lane = t & 31;
    const int rend = min((wid + 1) * 32, nblk);
    for (int r = wid * 32; r < rend; ++r) {
        const size_t i = (size_t)sperm[r];
        out[i * (2 * N_LEVELS) + lane] = s_acc[r * 33 + lane];
    }
}

// ---------------------------------------------------------------------------

extern "C" void kernel_launch(void* const* d_in, const int* in_sizes, int n_in,
                              void* d_out, int out_size) {
    const float* x      = (const float*)d_in[0];
    const float* tables = (const float*)d_in[1];
    float* out          = (float*)d_out;

    const int n = in_sizes[0] / 3;

    // Resolutions exactly as the reference computes them.
    Res16 rp;
    const double growth = pow(512.0 / 16.0, 1.0 / (double)(N_LEVELS - 1));
    for (int l = 0; l < N_LEVELS; ++l) {
        double r = 16.0 * pow(growth, (double)l);
        rp.r[l] = (float)(long long)r;
    }

    const int blocks = (n + BLOCK - 1) / BLOCK;

    zero_cnt_kernel<<<NB / 1024, 1024>>>();
    hist_kernel<<<blocks, BLOCK>>>(x, n);
    scan_kernel<<<1, 1024>>>();
    scatter_kernel<<<blocks, BLOCK>>>(x, n);
    hash_encode_kernel<<<blocks, BLOCK>>>(tables, out, rp, n);
}